// round 1
// baseline (speedup 1.0000x reference)
#include <cuda_runtime.h>
#include <cuda_bf16.h>

// CliffordLayerNorm: x[*, nb, 256], per-grade (popcount) layernorm within each
// 256-wide multivector block. weight[9], bias[9].
//
// Strategy: 8 lanes per MV (warp = 4 MVs = 4KB/iter). Each lane owns 32
// elements (in-thread bits 0,1 [j], 5,6,7 [k]; lane bits 2,3,4 [sub]).
// Grade sums via 3-step shuffle-XOR "grade polynomial" merge butterfly on
// relative grade arrays. One pass computes sum and sumsq; var = E[x2]-mean^2.
// Output is a single FMA per element with per-grade (a,b) selected via short
// SEL chains (grade offset is compile-time per element).

#define NG 9
#define CEPS 1e-5f

__global__ void __launch_bounds__(256, 2)
clifford_ln_kernel(const float* __restrict__ x,
                   const float* __restrict__ weight,
                   const float* __restrict__ bias,
                   float* __restrict__ out,
                   int num_groups)   // groups of 1024 floats (4 MVs)
{
    const int lane = threadIdx.x & 31;
    const int wid_global = blockIdx.x * (blockDim.x >> 5) + (threadIdx.x >> 5);
    const int nwarps = gridDim.x * (blockDim.x >> 5);
    const int sub = lane & 7;     // covers element bits 2,3,4
    const int mv  = lane >> 3;    // which of 4 MVs in the group
    const int p   = __popc(sub);  // relative grade base, 0..3

    // per-grade reciprocal counts C(8,g) = 1,8,28,56,70,56,28,8,1
    const float rc[NG] = {1.0f, 1.0f/8.0f, 1.0f/28.0f, 1.0f/56.0f, 1.0f/70.0f,
                          1.0f/56.0f, 1.0f/28.0f, 1.0f/8.0f, 1.0f};

    float wgt[NG], bs[NG];
#pragma unroll
    for (int g = 0; g < NG; ++g) {
        wgt[g] = __ldg(weight + g);
        bs[g]  = __ldg(bias + g);
    }

    for (int grp = wid_global; grp < num_groups; grp += nwarps) {
        const float4* __restrict__ xin =
            reinterpret_cast<const float4*>(x) + (size_t)grp * 256 + mv * 64 + sub;
        float4* __restrict__ xout =
            reinterpret_cast<float4*>(out) + (size_t)grp * 256 + mv * 64 + sub;

        // Load 8 float4 = 32 elements. float4 index k*8+sub within this MV's
        // 64 float4s -> element offset = k*32 + sub*4 + j.
        float4 v[8];
#pragma unroll
        for (int k = 0; k < 8; ++k) v[k] = xin[k * 8];

        // In-thread grade-relative partial sums. t = popc(k)+popc(j) in 0..5.
        float S[NG], Q[NG];
#pragma unroll
        for (int t = 0; t < NG; ++t) { S[t] = 0.0f; Q[t] = 0.0f; }
#pragma unroll
        for (int k = 0; k < 8; ++k) {
            const int pk = __popc(k);          // compile-time after unroll
            const float e0 = v[k].x, e1 = v[k].y, e2 = v[k].z, e3 = v[k].w;
            S[pk + 0] += e0;                   Q[pk + 0] = fmaf(e0, e0, Q[pk + 0]);
            S[pk + 1] += e1;                   Q[pk + 1] = fmaf(e1, e1, Q[pk + 1]);
            S[pk + 1] += e2;                   Q[pk + 1] = fmaf(e2, e2, Q[pk + 1]);
            S[pk + 2] += e3;                   Q[pk + 2] = fmaf(e3, e3, Q[pk + 2]);
        }

        // Butterfly merge over lane bits 0..2 (sub). Relative arrays grow
        // 6 -> 7 -> 8 -> 9. merged[t] = lower[t] + upper[t-1].
#pragma unroll
        for (int b = 0; b < 3; ++b) {
            const int n = 6 + b;               // current valid length
            const bool up = (sub >> b) & 1;
            float Sp[NG], Qp[NG];
#pragma unroll
            for (int t = 0; t < NG; ++t) {
                if (t < n) {
                    Sp[t] = __shfl_xor_sync(0xffffffffu, S[t], 1 << b);
                    Qp[t] = __shfl_xor_sync(0xffffffffu, Q[t], 1 << b);
                }
            }
            float Sn[NG], Qn[NG];
#pragma unroll
            for (int t = 0; t < NG; ++t) {
                if (t <= n) {
                    float lo_s = (t < n) ? (up ? Sp[t] : S[t]) : 0.0f;
                    float hi_s = (t > 0) ? (up ? S[t - 1] : Sp[t - 1]) : 0.0f;
                    Sn[t] = lo_s + hi_s;
                    float lo_q = (t < n) ? (up ? Qp[t] : Q[t]) : 0.0f;
                    float hi_q = (t > 0) ? (up ? Q[t - 1] : Qp[t - 1]) : 0.0f;
                    Qn[t] = lo_q + hi_q;
                }
            }
#pragma unroll
            for (int t = 0; t < NG; ++t) {
                if (t <= n) { S[t] = Sn[t]; Q[t] = Qn[t]; }
            }
        }

        // Now S[g], Q[g] are absolute grade sums of this MV (identical across
        // the 8 lanes of the group). Per-grade affine coefficients.
        float A[NG], B[NG];
#pragma unroll
        for (int g = 0; g < NG; ++g) {
            float m   = S[g] * rc[g];
            float var = fmaf(Q[g], rc[g], -m * m);
            float inv = rsqrtf(var + CEPS);
            float a   = inv * wgt[g];
            A[g] = a;
            B[g] = fmaf(-m, a, bs[g]);
        }

        // Select the 6 relative coefficients this lane needs: grade = p + t.
        float At[6], Bt[6];
#pragma unroll
        for (int t = 0; t < 6; ++t) {
            At[t] = (p == 0) ? A[t] : (p == 1) ? A[t + 1] : (p == 2) ? A[t + 2] : A[t + 3];
            Bt[t] = (p == 0) ? B[t] : (p == 1) ? B[t + 1] : (p == 2) ? B[t + 2] : B[t + 3];
        }

        // Output: one FMA per element, static coefficient index per (k,j).
#pragma unroll
        for (int k = 0; k < 8; ++k) {
            const int pk = __popc(k);
            float4 o;
            o.x = fmaf(v[k].x, At[pk + 0], Bt[pk + 0]);
            o.y = fmaf(v[k].y, At[pk + 1], Bt[pk + 1]);
            o.z = fmaf(v[k].z, At[pk + 1], Bt[pk + 1]);
            o.w = fmaf(v[k].w, At[pk + 2], Bt[pk + 2]);
            xout[k * 8] = o;
        }
    }
}

extern "C" void kernel_launch(void* const* d_in, const int* in_sizes, int n_in,
                              void* d_out, int out_size)
{
    const float* x      = (const float*)d_in[0];
    const float* weight = (const float*)d_in[1];
    const float* bias   = (const float*)d_in[2];
    float* out          = (float*)d_out;

    const int num_groups = in_sizes[0] / 1024;   // 4 MVs per warp-group
    const int threads = 256;
    const int blocks  = 1184;                    // 148 SMs * 8, grid-stride
    clifford_ln_kernel<<<blocks, threads>>>(x, weight, bias, out, num_groups);
}